// round 6
// baseline (speedup 1.0000x reference)
#include <cuda_runtime.h>
#include <math.h>
#include <stdint.h>

// Problem constants
#define Bsz  16
#define Cch  256
#define Och  256
#define Hh   64
#define Ww   64
#define HW   4096
#define Tdim 512
#define Eexp 4

// ---------------- device scratch (static, allocation-free) ----------------
__device__ float g_pooled[Bsz * Cch];                    // [b][c]
__device__ float g_rw[Bsz * Eexp];                       // [b][e]
__device__ float g_beff[Bsz * Och];                      // [b][o]
__device__ float g_weff[(size_t)Bsz * 9 * Och * Cch];    // [b][kk][o][c] (tf32-rounded)
__device__ float g_xt[(size_t)Bsz * HW * Cch];           // [b][s][c]     (NHWC, tf32-rounded)

// ---------------- PTX helpers (sm_80-baseline only) ----------------
__device__ __forceinline__ uint32_t smem_u32(const void* p) {
    uint32_t a;
    asm("{ .reg .u64 t; cvta.to.shared.u64 t, %1; cvt.u32.u64 %0, t; }" : "=r"(a) : "l"(p));
    return a;
}
__device__ __forceinline__ float to_tf32(float x) {
    uint32_t u;
    asm("cvt.rna.tf32.f32 %0, %1;" : "=r"(u) : "f"(x));
    return __uint_as_float(u);
}
__device__ __forceinline__ void cp16(uint32_t dst, const void* src, uint32_t nbytes) {
    asm volatile("cp.async.cg.shared.global [%0], [%1], 16, %2;"
                 :: "r"(dst), "l"(src), "r"(nbytes));
}
#define CP_COMMIT() asm volatile("cp.async.commit_group;" ::: "memory")
#define CP_WAIT1()  asm volatile("cp.async.wait_group 1;" ::: "memory")

__device__ __forceinline__ void ldsm4(uint32_t* d, uint32_t addr) {
    asm volatile("ldmatrix.sync.aligned.m8n8.x4.shared.b16 {%0,%1,%2,%3}, [%4];"
                 : "=r"(d[0]), "=r"(d[1]), "=r"(d[2]), "=r"(d[3]) : "r"(addr));
}
__device__ __forceinline__ void mma_tf32(float* d, const uint32_t* a, const uint32_t* b) {
    asm volatile(
        "mma.sync.aligned.m16n8k8.row.col.f32.tf32.tf32.f32 "
        "{%0,%1,%2,%3}, {%4,%5,%6,%7}, {%8,%9}, {%0,%1,%2,%3};"
        : "+f"(d[0]), "+f"(d[1]), "+f"(d[2]), "+f"(d[3])
        : "r"(a[0]), "r"(a[1]), "r"(a[2]), "r"(a[3]), "r"(b[0]), "r"(b[1]));
}

// ============================================================
// K0: transpose x -> x_t NHWC [b][s][c], tf32-rounded
// ============================================================
__global__ __launch_bounds__(256) void transpose_kernel(const float* __restrict__ x) {
    __shared__ float tile[32][33];
    int st = blockIdx.x;
    int ct = blockIdx.y;
    int b  = blockIdx.z;
    int tx = threadIdx.x & 31, ty = threadIdx.x >> 5;
    const float* xp = x + ((size_t)(b * Cch + ct * 32)) * HW + st * 32;
#pragma unroll
    for (int i = 0; i < 32; i += 8)
        tile[ty + i][tx] = xp[(size_t)(ty + i) * HW + tx];
    __syncthreads();
    float* op = g_xt + ((size_t)b * HW + st * 32) * Cch + ct * 32;
#pragma unroll
    for (int i = 0; i < 32; i += 8)
        op[(size_t)(ty + i) * Cch + tx] = to_tf32(tile[tx][ty + i]);
}

// ============================================================
// K1: pooled = mean over HxW.  One block per (b,c).
// ============================================================
__global__ __launch_bounds__(256) void pool_kernel(const float* __restrict__ x) {
    int bc = blockIdx.x;
    const float4* xp = (const float4*)(x + (size_t)bc * HW);
    int t = threadIdx.x;
    float s = 0.f;
#pragma unroll
    for (int i = 0; i < 4; i++) {
        float4 v = xp[t + i * 256];
        s += v.x + v.y + v.z + v.w;
    }
#pragma unroll
    for (int o = 16; o; o >>= 1) s += __shfl_down_sync(0xffffffffu, s, o);
    __shared__ float ws[8];
    if ((t & 31) == 0) ws[t >> 5] = s;
    __syncthreads();
    if (t < 8) {
        s = ws[t];
#pragma unroll
        for (int o = 4; o; o >>= 1) s += __shfl_down_sync(0xffu, s, o);
        if (t == 0) g_pooled[bc] = s * (1.0f / HW);
    }
}

// ============================================================
// K2: router.  One block per batch sample.
// ============================================================
__global__ __launch_bounds__(256) void router_kernel(
    const float* __restrict__ te,
    const float* __restrict__ Wq, const float* __restrict__ bq,
    const float* __restrict__ Wk, const float* __restrict__ bk,
    const float* __restrict__ Wv, const float* __restrict__ bv,
    const float* __restrict__ Wm1, const float* __restrict__ bm1,
    const float* __restrict__ Wm2, const float* __restrict__ bm2,
    const float* __restrict__ Wc, const float* __restrict__ bcv,
    const float* __restrict__ expert_b)
{
    int b = blockIdx.x;
    int t = threadIdx.x;
    __shared__ float s_te[Tdim];
    __shared__ float s_pool[Cch];
    __shared__ float s_xatt[Cch];
    __shared__ float s_h1[64];
    __shared__ float s_xmix[Cch];
    __shared__ float s_rw[Eexp];

    s_pool[t] = g_pooled[b * Cch + t];
    s_te[t]       = te[b * Tdim + t];
    s_te[t + 256] = te[b * Tdim + t + 256];
    __syncthreads();

    float q = bq[t];
    const float* wq = Wq + (size_t)t * Tdim;
    for (int i = 0; i < Tdim; i++) q = fmaf(wq[i], s_te[i], q);
    float kv = bk[t];
    const float* wk = Wk + (size_t)t * Cch;
    for (int i = 0; i < Cch; i++) kv = fmaf(wk[i], s_pool[i], kv);
    float v = bv[t];
    const float* wv = Wv + (size_t)t * Cch;
    for (int i = 0; i < Cch; i++) v = fmaf(wv[i], s_pool[i], v);

    float attn = 1.0f / (1.0f + expf(-(q * kv)));
    float xa = v * attn;
    s_xatt[t] = xa;
    __syncthreads();

    if (t < 64) {
        float a = bm1[t];
        const float* w = Wm1 + (size_t)t * Cch;
        for (int i = 0; i < Cch; i++) a = fmaf(w[i], s_xatt[i], a);
        s_h1[t] = 0.5f * a * (1.0f + erff(a * 0.7071067811865476f));
    }
    __syncthreads();

    float h = bm2[t];
    const float* w2 = Wm2 + (size_t)t * 64;
    for (int i = 0; i < 64; i++) h = fmaf(w2[i], s_h1[i], h);
    s_xmix[t] = xa + h;
    __syncthreads();

    if (t < Eexp) {
        float l = bcv[t];
        const float* wc = Wc + (size_t)t * Cch;
        for (int i = 0; i < Cch; i++) l = fmaf(wc[i], s_xmix[i], l);
        float r = tanhf(l);
        s_rw[t] = r;
        g_rw[b * Eexp + t] = r;
    }
    __syncthreads();

    float be = 0.f;
#pragma unroll
    for (int e = 0; e < Eexp; e++) be = fmaf(s_rw[e], expert_b[e * Och + t], be);
    g_beff[b * Och + t] = be;
}

// ============================================================
// K3: mix expert weights -> g_weff[b][kk][o][c], tf32-rounded.
// One block per o; expert slices staged coalesced through smem.
// ============================================================
__global__ __launch_bounds__(256) void mix_kernel(const float* __restrict__ ew) {
    __shared__ float s_ew[Eexp * Cch * 9];      // 9216 floats = 36 KB
    __shared__ float s_rw[Bsz * Eexp];
    int o = blockIdx.x;
    int t = threadIdx.x;
    if (t < Bsz * Eexp) s_rw[t] = g_rw[t];
#pragma unroll
    for (int e = 0; e < Eexp; e++)
        for (int i = t; i < Cch * 9; i += 256)
            s_ew[e * (Cch * 9) + i] = ew[((size_t)(e * Och + o)) * (Cch * 9) + i];
    __syncthreads();

    int c = t;
    float we[Eexp][9];
#pragma unroll
    for (int e = 0; e < Eexp; e++)
#pragma unroll
        for (int k = 0; k < 9; k++) we[e][k] = s_ew[e * (Cch * 9) + c * 9 + k];

#pragma unroll 1
    for (int b = 0; b < Bsz; b++) {
        float r0 = s_rw[b * 4 + 0], r1 = s_rw[b * 4 + 1];
        float r2 = s_rw[b * 4 + 2], r3 = s_rw[b * 4 + 3];
#pragma unroll
        for (int k = 0; k < 9; k++) {
            float w = r0 * we[0][k] + r1 * we[1][k] + r2 * we[2][k] + r3 * we[3][k];
            g_weff[(((size_t)(b * 9 + k) * Och + o) << 8) + c] = to_tf32(w);
        }
    }
}

// ============================================================
// K4: mma.sync TF32 implicit-GEMM conv, ldmatrix fragment loads.
// CTA tile: 128 spatial (M) x 128 O (N), K = 9*256 in 72 chunks of 32.
// 8 warps, warp tile 64x32. 3-stage cp.async pipeline.
// ============================================================
#define BM 128
#define BN 128
#define BK 32
#define LDA 36
#define STAGE_FLOATS ((BM + BN) * LDA)          // 9216 floats = 36864 B
#define CONV_SMEM (3 * STAGE_FLOATS * 4)        // 110592 B

__device__ __forceinline__ void load_chunk(uint32_t sA, uint32_t sB,
                                           const float* __restrict__ xtb,
                                           const float* __restrict__ wbB,
                                           int chunk, int tid, int h0)
{
    int kk = chunk >> 3;
    int c0 = (chunk & 7) * 32;
    int dh = kk / 3 - 1, dw = kk % 3 - 1;
    const float* wb = wbB + (size_t)kk * (Och * Cch);
#pragma unroll
    for (int i = 0; i < 4; i++) {
        int idx = i * 256 + tid;
        int r = idx >> 3, cq = idx & 7;
        int hh = h0 + (r >> 6) + dh;
        int ww = (r & 63) + dw;
        bool ok = ((unsigned)hh < 64u) && ((unsigned)ww < 64u);
        const float* g = ok ? (xtb + (size_t)(hh * 64 + ww) * Cch + c0 + cq * 4) : xtb;
        cp16(sA + (uint32_t)(r * LDA + cq * 4) * 4, g, ok ? 16u : 0u);
    }
#pragma unroll
    for (int i = 0; i < 4; i++) {
        int idx = i * 256 + tid;
        int r = idx >> 3, cq = idx & 7;
        const float* g = wb + (size_t)r * Cch + c0 + cq * 4;
        cp16(sB + (uint32_t)(r * LDA + cq * 4) * 4, g, 16u);
    }
    CP_COMMIT();
}

__global__ __launch_bounds__(256) void conv_mma_kernel(float* __restrict__ out) {
    extern __shared__ float smf[];
    uint32_t sbase = smem_u32(smf);
    int tid = threadIdx.x;
    int wid = tid >> 5, lane = tid & 31;
    int warp_m = wid & 1;       // 2 x 64 along M
    int warp_n = wid >> 1;      // 4 x 32 along N

    int nt = blockIdx.x;
    int bn = blockIdx.y;
    int b  = blockIdx.z;
    int h0 = nt * 2;

    const float* xtb = g_xt + (size_t)b * HW * Cch;
    const float* wbB = g_weff + ((size_t)(b * 9) * Och + bn * BN) * Cch;

    uint32_t stA[3], stB[3];
#pragma unroll
    for (int s = 0; s < 3; s++) {
        stA[s] = sbase + (uint32_t)(s * STAGE_FLOATS) * 4;
        stB[s] = stA[s] + (uint32_t)(BM * LDA) * 4;
    }

    // ldmatrix per-thread base offsets.
    // A x4 tiles: (rows m0+0..7 @k0), (m0+8..15 @k0), (m0+0..7 @k0+4), (m0+8..15 @k0+4)
    // B x4 tiles: (n0+0..7 @k0), (n0+0..7 @k0+4), (n0+8..15 @k0), (n0+8..15 @k0+4)
    int g8 = lane >> 3, r8 = lane & 7;
    uint32_t a_base = (uint32_t)(((warp_m * 64 + r8 + ((g8 & 1) << 3)) * LDA + ((g8 >> 1) << 2)) * 4);
    uint32_t b_base = (uint32_t)(((warp_n * 32 + r8 + ((g8 >> 1) << 3)) * LDA + ((g8 & 1) << 2)) * 4);

    float acc[4][4][4];
#pragma unroll
    for (int i = 0; i < 4; i++)
#pragma unroll
        for (int j = 0; j < 4; j++)
#pragma unroll
            for (int k = 0; k < 4; k++) acc[i][j][k] = 0.f;

    load_chunk(stA[0], stB[0], xtb, wbB, 0, tid, h0);
    load_chunk(stA[1], stB[1], xtb, wbB, 1, tid, h0);
    CP_WAIT1();
    __syncthreads();

    int fr = lane >> 2;
    int fc = lane & 3;

#pragma unroll 1
    for (int i = 0; i < 72; i++) {
        if (i + 2 < 72) {
            int s2 = (i + 2) % 3;
            load_chunk(stA[s2], stB[s2], xtb, wbB, i + 2, tid, h0);
        } else {
            CP_COMMIT();
        }
        uint32_t Asm = stA[i % 3] + a_base;
        uint32_t Bsm = stA[i % 3] + (uint32_t)(BM * LDA) * 4 + b_base;

#pragma unroll
        for (int k8 = 0; k8 < 4; k8++) {
            uint32_t koff = (uint32_t)(k8 * 8 * 4);
            uint32_t af[4][4], bf[4][2];
#pragma unroll
            for (int mt = 0; mt < 4; mt++)
                ldsm4(af[mt], Asm + koff + (uint32_t)(mt * 16 * LDA * 4));
#pragma unroll
            for (int p = 0; p < 2; p++) {
                uint32_t tmp[4];
                ldsm4(tmp, Bsm + koff + (uint32_t)(p * 16 * LDA * 4));
                bf[2 * p][0] = tmp[0]; bf[2 * p][1] = tmp[1];
                bf[2 * p + 1][0] = tmp[2]; bf[2 * p + 1][1] = tmp[3];
            }
#pragma unroll
            for (int mt = 0; mt < 4; mt++)
#pragma unroll
                for (int nt2 = 0; nt2 < 4; nt2++)
                    mma_tf32(acc[mt][nt2], af[mt], bf[nt2]);
        }
        CP_WAIT1();
        __syncthreads();
    }

    // ---- epilogue: stage acc through smem, coalesced float4 stores ----
    float* ep = smf;
#pragma unroll
    for (int mt = 0; mt < 4; mt++) {
#pragma unroll
        for (int nt2 = 0; nt2 < 4; nt2++) {
            int rr = warp_m * 64 + mt * 16 + fr;
            int cc = warp_n * 32 + nt2 * 8 + 2 * fc;
            ep[cc * 132 + rr]           = acc[mt][nt2][0];
            ep[(cc + 1) * 132 + rr]     = acc[mt][nt2][1];
            ep[cc * 132 + rr + 8]       = acc[mt][nt2][2];
            ep[(cc + 1) * 132 + rr + 8] = acc[mt][nt2][3];
        }
    }
    __syncthreads();

    const float* bias = g_beff + b * Och + bn * BN;
    size_t obase = ((size_t)(b * Och + bn * BN)) * HW + nt * BM;
#pragma unroll
    for (int i = 0; i < 16; i++) {
        int idx = i * 256 + tid;
        int o = idx >> 5, q = idx & 31;
        float bz = bias[o];
        const float* s = ep + o * 132 + q * 4;
        float4 v = make_float4(s[0] + bz, s[1] + bz, s[2] + bz, s[3] + bz);
        *(float4*)(out + obase + (size_t)o * HW + q * 4) = v;
    }
}

// ============================================================
// launch
// ============================================================
extern "C" void kernel_launch(void* const* d_in, const int* in_sizes, int n_in,
                              void* d_out, int out_size)
{
    const float* x        = (const float*)d_in[0];
    const float* time_emb = (const float*)d_in[1];
    const float* Wq  = (const float*)d_in[2];
    const float* bq  = (const float*)d_in[3];
    const float* Wk  = (const float*)d_in[4];
    const float* bk  = (const float*)d_in[5];
    const float* Wv  = (const float*)d_in[6];
    const float* bv  = (const float*)d_in[7];
    const float* Wm1 = (const float*)d_in[8];
    const float* bm1 = (const float*)d_in[9];
    const float* Wm2 = (const float*)d_in[10];
    const float* bm2 = (const float*)d_in[11];
    const float* Wc  = (const float*)d_in[12];
    const float* bc  = (const float*)d_in[13];
    const float* expert_w = (const float*)d_in[14];
    const float* expert_b = (const float*)d_in[15];
    float* out = (float*)d_out;

    cudaFuncSetAttribute(conv_mma_kernel, cudaFuncAttributeMaxDynamicSharedMemorySize, CONV_SMEM);

    dim3 tgrid(HW / 32, Cch / 32, Bsz);
    transpose_kernel<<<tgrid, 256>>>(x);
    pool_kernel<<<Bsz * Cch, 256>>>(x);
    router_kernel<<<Bsz, 256>>>(time_emb, Wq, bq, Wk, bk, Wv, bv,
                                Wm1, bm1, Wm2, bm2, Wc, bc, expert_b);
    mix_kernel<<<Och, 256>>>(expert_w);

    dim3 grid(HW / BM, Och / BN, Bsz);
    conv_mma_kernel<<<grid, 256, CONV_SMEM>>>(out);
}

// round 7
// speedup vs baseline: 1.1478x; 1.1478x over previous
#include <cuda_runtime.h>
#include <math.h>
#include <stdint.h>

// Problem constants
#define Bsz  16
#define Cch  256
#define Och  256
#define Hh   64
#define Ww   64
#define HW   4096
#define Tdim 512
#define Eexp 4

// ---------------- device scratch (static, allocation-free) ----------------
__device__ float g_pp[Bsz * 128 * Cch];                  // [b][st][c] partial pools
__device__ float g_rw[Bsz * Eexp];                       // [b][e]
__device__ float g_beff[Bsz * Och];                      // [b][o]
__device__ float g_weff[(size_t)Bsz * 9 * Och * Cch];    // [b][kk][o][c] (tf32-rounded)
__device__ float g_xt[(size_t)Bsz * HW * Cch];           // [b][s][c]     (NHWC, tf32-rounded)

// ---------------- PTX helpers (sm_80-baseline only) ----------------
__device__ __forceinline__ uint32_t smem_u32(const void* p) {
    uint32_t a;
    asm("{ .reg .u64 t; cvta.to.shared.u64 t, %1; cvt.u32.u64 %0, t; }" : "=r"(a) : "l"(p));
    return a;
}
__device__ __forceinline__ float to_tf32(float x) {
    uint32_t u;
    asm("cvt.rna.tf32.f32 %0, %1;" : "=r"(u) : "f"(x));
    return __uint_as_float(u);
}
__device__ __forceinline__ void cp16(uint32_t dst, const void* src, uint32_t nbytes) {
    asm volatile("cp.async.cg.shared.global [%0], [%1], 16, %2;"
                 :: "r"(dst), "l"(src), "r"(nbytes));
}
#define CP_COMMIT() asm volatile("cp.async.commit_group;" ::: "memory")
#define CP_WAIT1()  asm volatile("cp.async.wait_group 1;" ::: "memory")

__device__ __forceinline__ void mma_tf32(float* d, const uint32_t* a, const uint32_t* b) {
    asm volatile(
        "mma.sync.aligned.m16n8k8.row.col.f32.tf32.tf32.f32 "
        "{%0,%1,%2,%3}, {%4,%5,%6,%7}, {%8,%9}, {%0,%1,%2,%3};"
        : "+f"(d[0]), "+f"(d[1]), "+f"(d[2]), "+f"(d[3])
        : "r"(a[0]), "r"(a[1]), "r"(a[2]), "r"(a[3]), "r"(b[0]), "r"(b[1]));
}

// ============================================================
// K0: fused transpose + partial pool.
// x[b][c][s] -> g_xt[b][s][c] (tf32-rounded), and per-tile channel
// partial sums -> g_pp[b][st][c]  (deterministic, no atomics).
// ============================================================
__global__ __launch_bounds__(256) void transpose_pool_kernel(const float* __restrict__ x) {
    __shared__ float tile[32][33];
    int st = blockIdx.x;   // spatial tile (HW/32 = 128)
    int ct = blockIdx.y;   // channel tile (256/32 = 8)
    int b  = blockIdx.z;
    int tx = threadIdx.x & 31, ty = threadIdx.x >> 5;
    const float* xp = x + ((size_t)(b * Cch + ct * 32)) * HW + st * 32;
#pragma unroll
    for (int i = 0; i < 32; i += 8)
        tile[ty + i][tx] = xp[(size_t)(ty + i) * HW + tx];   // tile[c_local][s_local]
    __syncthreads();
    float* op = g_xt + ((size_t)b * HW + st * 32) * Cch + ct * 32;
#pragma unroll
    for (int i = 0; i < 32; i += 8)
        op[(size_t)(ty + i) * Cch + tx] = to_tf32(tile[tx][ty + i]);

    // partial pool: warp ty reduces channels [ty*4, ty*4+4)
#pragma unroll
    for (int j = 0; j < 4; j++) {
        int c = ty * 4 + j;
        float s = tile[c][tx];
#pragma unroll
        for (int o = 16; o; o >>= 1) s += __shfl_down_sync(0xffffffffu, s, o);
        if (tx == 0)
            g_pp[((size_t)(b * 128 + st)) * Cch + ct * 32 + c] = s;
    }
}

// ============================================================
// K1: router.  One block per batch sample; sums pool partials first.
// ============================================================
__global__ __launch_bounds__(256) void router_kernel(
    const float* __restrict__ te,
    const float* __restrict__ Wq, const float* __restrict__ bq,
    const float* __restrict__ Wk, const float* __restrict__ bk,
    const float* __restrict__ Wv, const float* __restrict__ bv,
    const float* __restrict__ Wm1, const float* __restrict__ bm1,
    const float* __restrict__ Wm2, const float* __restrict__ bm2,
    const float* __restrict__ Wc, const float* __restrict__ bcv,
    const float* __restrict__ expert_b)
{
    int b = blockIdx.x;
    int t = threadIdx.x;
    __shared__ float s_te[Tdim];
    __shared__ float s_pool[Cch];
    __shared__ float s_xatt[Cch];
    __shared__ float s_h1[64];
    __shared__ float s_xmix[Cch];
    __shared__ float s_rw[Eexp];

    // pooled[c] = (1/HW) * sum_st g_pp[b][st][c]   (coalesced across threads)
    {
        float s = 0.f;
        const float* pp = g_pp + (size_t)b * 128 * Cch + t;
#pragma unroll 4
        for (int st = 0; st < 128; st++) s += pp[(size_t)st * Cch];
        s_pool[t] = s * (1.0f / HW);
    }
    s_te[t]       = te[b * Tdim + t];
    s_te[t + 256] = te[b * Tdim + t + 256];
    __syncthreads();

    float q = bq[t];
    const float* wq = Wq + (size_t)t * Tdim;
    for (int i = 0; i < Tdim; i++) q = fmaf(wq[i], s_te[i], q);
    float kv = bk[t];
    const float* wk = Wk + (size_t)t * Cch;
    for (int i = 0; i < Cch; i++) kv = fmaf(wk[i], s_pool[i], kv);
    float v = bv[t];
    const float* wv = Wv + (size_t)t * Cch;
    for (int i = 0; i < Cch; i++) v = fmaf(wv[i], s_pool[i], v);

    float attn = 1.0f / (1.0f + expf(-(q * kv)));
    float xa = v * attn;
    s_xatt[t] = xa;
    __syncthreads();

    if (t < 64) {
        float a = bm1[t];
        const float* w = Wm1 + (size_t)t * Cch;
        for (int i = 0; i < Cch; i++) a = fmaf(w[i], s_xatt[i], a);
        s_h1[t] = 0.5f * a * (1.0f + erff(a * 0.7071067811865476f));
    }
    __syncthreads();

    float h = bm2[t];
    const float* w2 = Wm2 + (size_t)t * 64;
    for (int i = 0; i < 64; i++) h = fmaf(w2[i], s_h1[i], h);
    s_xmix[t] = xa + h;
    __syncthreads();

    if (t < Eexp) {
        float l = bcv[t];
        const float* wc = Wc + (size_t)t * Cch;
        for (int i = 0; i < Cch; i++) l = fmaf(wc[i], s_xmix[i], l);
        float r = tanhf(l);
        s_rw[t] = r;
        g_rw[b * Eexp + t] = r;
    }
    __syncthreads();

    float be = 0.f;
#pragma unroll
    for (int e = 0; e < Eexp; e++) be = fmaf(s_rw[e], expert_b[e * Och + t], be);
    g_beff[b * Och + t] = be;
}

// ============================================================
// K2: mix expert weights -> g_weff[b][kk][o][c], tf32-rounded.
// (R5 version — direct loads, one thread per (c,o).)
// ============================================================
__global__ __launch_bounds__(256) void mix_kernel(const float* __restrict__ ew) {
    __shared__ float s_rw[Bsz * Eexp];
    if (threadIdx.x < Bsz * Eexp) s_rw[threadIdx.x] = g_rw[threadIdx.x];
    __syncthreads();

    int gid = blockIdx.x * 256 + threadIdx.x;   // 0 .. 65535
    int c = gid & 255;
    int o = gid >> 8;

    float we[Eexp][9];
#pragma unroll
    for (int e = 0; e < Eexp; e++) {
        const float* p = ew + ((size_t)((e * Och + o) * Cch + c)) * 9;
#pragma unroll
        for (int k = 0; k < 9; k++) we[e][k] = p[k];
    }
#pragma unroll 1
    for (int b = 0; b < Bsz; b++) {
        float r0 = s_rw[b * 4 + 0], r1 = s_rw[b * 4 + 1];
        float r2 = s_rw[b * 4 + 2], r3 = s_rw[b * 4 + 3];
#pragma unroll
        for (int k = 0; k < 9; k++) {
            float w = r0 * we[0][k] + r1 * we[1][k] + r2 * we[2][k] + r3 * we[3][k];
            g_weff[(((size_t)(b * 9 + k) * Och + o) << 8) + c] = to_tf32(w);
        }
    }
}

// ============================================================
// K3: mma.sync TF32 implicit-GEMM conv (R5 mainloop, scalar LDS).
// CTA tile: 128 spatial (M) x 128 O (N), K = 9*256 in 72 chunks of 32.
// 8 warps, warp tile 64x32. 3-stage cp.async pipeline.
// ============================================================
#define BM 128
#define BN 128
#define BK 32
#define LDA 36
#define STAGE_FLOATS ((BM + BN) * LDA)          // 9216 floats = 36864 B
#define CONV_SMEM (3 * STAGE_FLOATS * 4)        // 110592 B

__device__ __forceinline__ void load_chunk(uint32_t sA, uint32_t sB,
                                           const float* __restrict__ xtb,
                                           const float* __restrict__ wbB,
                                           int chunk, int tid, int h0)
{
    int kk = chunk >> 3;
    int c0 = (chunk & 7) * 32;
    int dh = kk / 3 - 1, dw = kk % 3 - 1;
    const float* wb = wbB + (size_t)kk * (Och * Cch);
#pragma unroll
    for (int i = 0; i < 4; i++) {
        int idx = i * 256 + tid;
        int r = idx >> 3, cq = idx & 7;
        int hh = h0 + (r >> 6) + dh;
        int ww = (r & 63) + dw;
        bool ok = ((unsigned)hh < 64u) && ((unsigned)ww < 64u);
        const float* g = ok ? (xtb + (size_t)(hh * 64 + ww) * Cch + c0 + cq * 4) : xtb;
        cp16(sA + (uint32_t)(r * LDA + cq * 4) * 4, g, ok ? 16u : 0u);
    }
#pragma unroll
    for (int i = 0; i < 4; i++) {
        int idx = i * 256 + tid;
        int r = idx >> 3, cq = idx & 7;
        const float* g = wb + (size_t)r * Cch + c0 + cq * 4;
        cp16(sB + (uint32_t)(r * LDA + cq * 4) * 4, g, 16u);
    }
    CP_COMMIT();
}

__global__ __launch_bounds__(256) void conv_mma_kernel(float* __restrict__ out) {
    extern __shared__ float smf[];
    uint32_t sbase = smem_u32(smf);
    int tid = threadIdx.x;
    int wid = tid >> 5, lane = tid & 31;
    int warp_m = wid & 1;       // 2 x 64 along M
    int warp_n = wid >> 1;      // 4 x 32 along N

    int nt = blockIdx.x;
    int bn = blockIdx.y;
    int b  = blockIdx.z;
    int h0 = nt * 2;

    const float* xtb = g_xt + (size_t)b * HW * Cch;
    const float* wbB = g_weff + ((size_t)(b * 9) * Och + bn * BN) * Cch;

    uint32_t stA[3], stB[3];
#pragma unroll
    for (int s = 0; s < 3; s++) {
        stA[s] = sbase + (uint32_t)(s * STAGE_FLOATS) * 4;
        stB[s] = stA[s] + (uint32_t)(BM * LDA) * 4;
    }

    float acc[4][4][4];
#pragma unroll
    for (int i = 0; i < 4; i++)
#pragma unroll
        for (int j = 0; j < 4; j++)
#pragma unroll
            for (int k = 0; k < 4; k++) acc[i][j][k] = 0.f;

    load_chunk(stA[0], stB[0], xtb, wbB, 0, tid, h0);
    load_chunk(stA[1], stB[1], xtb, wbB, 1, tid, h0);
    CP_WAIT1();
    __syncthreads();

    int fr = lane >> 2;
    int fc = lane & 3;

#pragma unroll 1
    for (int i = 0; i < 72; i++) {
        if (i + 2 < 72) {
            int s2 = (i + 2) % 3;
            load_chunk(stA[s2], stB[s2], xtb, wbB, i + 2, tid, h0);
        } else {
            CP_COMMIT();
        }
        const float* As = smf + (size_t)(i % 3) * STAGE_FLOATS;
        const float* Bs = As + BM * LDA;

#pragma unroll
        for (int k8 = 0; k8 < 4; k8++) {
            int k0 = k8 * 8;
            uint32_t af[4][4], bf[4][2];
#pragma unroll
            for (int mt = 0; mt < 4; mt++) {
                int m0 = warp_m * 64 + mt * 16;
                af[mt][0] = __float_as_uint(As[(m0 + fr) * LDA + k0 + fc]);
                af[mt][1] = __float_as_uint(As[(m0 + fr + 8) * LDA + k0 + fc]);
                af[mt][2] = __float_as_uint(As[(m0 + fr) * LDA + k0 + fc + 4]);
                af[mt][3] = __float_as_uint(As[(m0 + fr + 8) * LDA + k0 + fc + 4]);
            }
#pragma unroll
            for (int nt2 = 0; nt2 < 4; nt2++) {
                int n0 = warp_n * 32 + nt2 * 8;
                bf[nt2][0] = __float_as_uint(Bs[(n0 + fr) * LDA + k0 + fc]);
                bf[nt2][1] = __float_as_uint(Bs[(n0 + fr) * LDA + k0 + fc + 4]);
            }
#pragma unroll
            for (int mt = 0; mt < 4; mt++)
#pragma unroll
                for (int nt2 = 0; nt2 < 4; nt2++)
                    mma_tf32(acc[mt][nt2], af[mt], bf[nt2]);
        }
        CP_WAIT1();
        __syncthreads();
    }

    // ---- epilogue: stage acc through smem, coalesced float4 stores ----
    float* ep = smf;
#pragma unroll
    for (int mt = 0; mt < 4; mt++) {
#pragma unroll
        for (int nt2 = 0; nt2 < 4; nt2++) {
            int rr = warp_m * 64 + mt * 16 + fr;
            int cc = warp_n * 32 + nt2 * 8 + 2 * fc;
            ep[cc * 132 + rr]           = acc[mt][nt2][0];
            ep[(cc + 1) * 132 + rr]     = acc[mt][nt2][1];
            ep[cc * 132 + rr + 8]       = acc[mt][nt2][2];
            ep[(cc + 1) * 132 + rr + 8] = acc[mt][nt2][3];
        }
    }
    __syncthreads();

    const float* bias = g_beff + b * Och + bn * BN;
    size_t obase = ((size_t)(b * Och + bn * BN)) * HW + nt * BM;
#pragma unroll
    for (int i = 0; i < 16; i++) {
        int idx = i * 256 + tid;
        int o = idx >> 5, q = idx & 31;
        float bz = bias[o];
        const float* s = ep + o * 132 + q * 4;
        float4 v = make_float4(s[0] + bz, s[1] + bz, s[2] + bz, s[3] + bz);
        *(float4*)(out + obase + (size_t)o * HW + q * 4) = v;
    }
}

// ============================================================
// launch — 3 prologue kernels, conv is the 4th launch (profiled slot)
// ============================================================
extern "C" void kernel_launch(void* const* d_in, const int* in_sizes, int n_in,
                              void* d_out, int out_size)
{
    const float* x        = (const float*)d_in[0];
    const float* time_emb = (const float*)d_in[1];
    const float* Wq  = (const float*)d_in[2];
    const float* bq  = (const float*)d_in[3];
    const float* Wk  = (const float*)d_in[4];
    const float* bk  = (const float*)d_in[5];
    const float* Wv  = (const float*)d_in[6];
    const float* bv  = (const float*)d_in[7];
    const float* Wm1 = (const float*)d_in[8];
    const float* bm1 = (const float*)d_in[9];
    const float* Wm2 = (const float*)d_in[10];
    const float* bm2 = (const float*)d_in[11];
    const float* Wc  = (const float*)d_in[12];
    const float* bc  = (const float*)d_in[13];
    const float* expert_w = (const float*)d_in[14];
    const float* expert_b = (const float*)d_in[15];
    float* out = (float*)d_out;

    cudaFuncSetAttribute(conv_mma_kernel, cudaFuncAttributeMaxDynamicSharedMemorySize, CONV_SMEM);

    dim3 tgrid(HW / 32, Cch / 32, Bsz);
    transpose_pool_kernel<<<tgrid, 256>>>(x);
    router_kernel<<<Bsz, 256>>>(time_emb, Wq, bq, Wk, bk, Wv, bv,
                                Wm1, bm1, Wm2, bm2, Wc, bc, expert_b);
    mix_kernel<<<(Och * Cch) / 256, 256>>>(expert_w);

    dim3 grid(HW / BM, Och / BN, Bsz);
    conv_mma_kernel<<<grid, 256, CONV_SMEM>>>(out);
}

// round 8
// speedup vs baseline: 1.7430x; 1.5186x over previous
#include <cuda_runtime.h>
#include <cuda_fp16.h>
#include <math.h>
#include <stdint.h>

// Problem constants
#define Bsz  16
#define Cch  256
#define Och  256
#define Hh   64
#define Ww   64
#define HW   4096
#define Tdim 512
#define Eexp 4

// ---------------- device scratch (static, allocation-free) ----------------
__device__ float  g_pp[Bsz * 128 * Cch];                  // [b][st][c] partial pools
__device__ float  g_rw[Bsz * Eexp];                       // [b][e]
__device__ float  g_beff[Bsz * Och];                      // [b][o]
__device__ __half g_weff[(size_t)Bsz * 9 * Och * Cch];    // [b][kk][o][c] fp16
__device__ __half g_xt[(size_t)Bsz * HW * Cch];           // [b][s][c]     NHWC fp16

// ---------------- PTX helpers (sm_80-baseline only) ----------------
__device__ __forceinline__ uint32_t smem_u32(const void* p) {
    uint32_t a;
    asm("{ .reg .u64 t; cvta.to.shared.u64 t, %1; cvt.u32.u64 %0, t; }" : "=r"(a) : "l"(p));
    return a;
}
__device__ __forceinline__ void cp16(uint32_t dst, const void* src, uint32_t nbytes) {
    asm volatile("cp.async.cg.shared.global [%0], [%1], 16, %2;"
                 :: "r"(dst), "l"(src), "r"(nbytes));
}
#define CP_COMMIT() asm volatile("cp.async.commit_group;" ::: "memory")
#define CP_WAIT1()  asm volatile("cp.async.wait_group 1;" ::: "memory")

__device__ __forceinline__ void mma_f16(float* d, const uint32_t* a, const uint32_t* b) {
    asm volatile(
        "mma.sync.aligned.m16n8k16.row.col.f32.f16.f16.f32 "
        "{%0,%1,%2,%3}, {%4,%5,%6,%7}, {%8,%9}, {%0,%1,%2,%3};"
        : "+f"(d[0]), "+f"(d[1]), "+f"(d[2]), "+f"(d[3])
        : "r"(a[0]), "r"(a[1]), "r"(a[2]), "r"(a[3]), "r"(b[0]), "r"(b[1]));
}

// ============================================================
// K0: fused transpose + partial pool.
// x[b][c][s] -> g_xt[b][s][c] (fp16), per-tile pools -> g_pp.
// ============================================================
__global__ __launch_bounds__(256) void transpose_pool_kernel(const float* __restrict__ x) {
    __shared__ float tile[32][33];
    int st = blockIdx.x;   // spatial tile (HW/32 = 128)
    int ct = blockIdx.y;   // channel tile (256/32 = 8)
    int b  = blockIdx.z;
    int tx = threadIdx.x & 31, ty = threadIdx.x >> 5;
    const float* xp = x + ((size_t)(b * Cch + ct * 32)) * HW + st * 32;
#pragma unroll
    for (int i = 0; i < 32; i += 8)
        tile[ty + i][tx] = xp[(size_t)(ty + i) * HW + tx];   // tile[c_local][s_local]
    __syncthreads();
    __half* op = g_xt + ((size_t)b * HW + st * 32) * Cch + ct * 32;
#pragma unroll
    for (int i = 0; i < 32; i += 8)
        op[(size_t)(ty + i) * Cch + tx] = __float2half_rn(tile[tx][ty + i]);

    // partial pool: warp ty reduces channels [ty*4, ty*4+4)
#pragma unroll
    for (int j = 0; j < 4; j++) {
        int c = ty * 4 + j;
        float s = tile[c][tx];
#pragma unroll
        for (int o = 16; o; o >>= 1) s += __shfl_down_sync(0xffffffffu, s, o);
        if (tx == 0)
            g_pp[((size_t)(b * 128 + st)) * Cch + ct * 32 + c] = s;
    }
}

// ============================================================
// K1: router.  One block per batch sample.
// ============================================================
__global__ __launch_bounds__(256) void router_kernel(
    const float* __restrict__ te,
    const float* __restrict__ Wq, const float* __restrict__ bq,
    const float* __restrict__ Wk, const float* __restrict__ bk,
    const float* __restrict__ Wv, const float* __restrict__ bv,
    const float* __restrict__ Wm1, const float* __restrict__ bm1,
    const float* __restrict__ Wm2, const float* __restrict__ bm2,
    const float* __restrict__ Wc, const float* __restrict__ bcv,
    const float* __restrict__ expert_b)
{
    int b = blockIdx.x;
    int t = threadIdx.x;
    __shared__ float s_te[Tdim];
    __shared__ float s_pool[Cch];
    __shared__ float s_xatt[Cch];
    __shared__ float s_h1[64];
    __shared__ float s_xmix[Cch];
    __shared__ float s_rw[Eexp];

    {
        float s = 0.f;
        const float* pp = g_pp + (size_t)b * 128 * Cch + t;
#pragma unroll 4
        for (int st = 0; st < 128; st++) s += pp[(size_t)st * Cch];
        s_pool[t] = s * (1.0f / HW);
    }
    s_te[t]       = te[b * Tdim + t];
    s_te[t + 256] = te[b * Tdim + t + 256];
    __syncthreads();

    float q = bq[t];
    const float* wq = Wq + (size_t)t * Tdim;
    for (int i = 0; i < Tdim; i++) q = fmaf(wq[i], s_te[i], q);
    float kv = bk[t];
    const float* wk = Wk + (size_t)t * Cch;
    for (int i = 0; i < Cch; i++) kv = fmaf(wk[i], s_pool[i], kv);
    float v = bv[t];
    const float* wv = Wv + (size_t)t * Cch;
    for (int i = 0; i < Cch; i++) v = fmaf(wv[i], s_pool[i], v);

    float attn = 1.0f / (1.0f + expf(-(q * kv)));
    float xa = v * attn;
    s_xatt[t] = xa;
    __syncthreads();

    if (t < 64) {
        float a = bm1[t];
        const float* w = Wm1 + (size_t)t * Cch;
        for (int i = 0; i < Cch; i++) a = fmaf(w[i], s_xatt[i], a);
        s_h1[t] = 0.5f * a * (1.0f + erff(a * 0.7071067811865476f));
    }
    __syncthreads();

    float h = bm2[t];
    const float* w2 = Wm2 + (size_t)t * 64;
    for (int i = 0; i < 64; i++) h = fmaf(w2[i], s_h1[i], h);
    s_xmix[t] = xa + h;
    __syncthreads();

    if (t < Eexp) {
        float l = bcv[t];
        const float* wc = Wc + (size_t)t * Cch;
        for (int i = 0; i < Cch; i++) l = fmaf(wc[i], s_xmix[i], l);
        float r = tanhf(l);
        s_rw[t] = r;
        g_rw[b * Eexp + t] = r;
    }
    __syncthreads();

    float be = 0.f;
#pragma unroll
    for (int e = 0; e < Eexp; e++) be = fmaf(s_rw[e], expert_b[e * Och + t], be);
    g_beff[b * Och + t] = be;
}

// ============================================================
// K2: mix expert weights -> g_weff[b][kk][o][c] fp16.
// ============================================================
__global__ __launch_bounds__(256) void mix_kernel(const float* __restrict__ ew) {
    __shared__ float s_rw[Bsz * Eexp];
    if (threadIdx.x < Bsz * Eexp) s_rw[threadIdx.x] = g_rw[threadIdx.x];
    __syncthreads();

    int gid = blockIdx.x * 256 + threadIdx.x;   // 0 .. 65535
    int c = gid & 255;
    int o = gid >> 8;

    float we[Eexp][9];
#pragma unroll
    for (int e = 0; e < Eexp; e++) {
        const float* p = ew + ((size_t)((e * Och + o) * Cch + c)) * 9;
#pragma unroll
        for (int k = 0; k < 9; k++) we[e][k] = p[k];
    }
#pragma unroll 1
    for (int b = 0; b < Bsz; b++) {
        float r0 = s_rw[b * 4 + 0], r1 = s_rw[b * 4 + 1];
        float r2 = s_rw[b * 4 + 2], r3 = s_rw[b * 4 + 3];
#pragma unroll
        for (int k = 0; k < 9; k++) {
            float w = r0 * we[0][k] + r1 * we[1][k] + r2 * we[2][k] + r3 * we[3][k];
            g_weff[(((size_t)(b * 9 + k) * Och + o) << 8) + c] = __float2half_rn(w);
        }
    }
}

// ============================================================
// K3: fp16 mma.sync implicit-GEMM conv.
// CTA tile: 128 spatial (M) x 128 O (N), K = 9*256 in 36 chunks of 64.
// 8 warps, warp tile 64x32 (m16n8k16). 3-stage cp.async pipeline.
// ============================================================
#define BM 128
#define BN 128
#define BKc 64
#define LDA_H 72                                 // halves per smem row
#define LDA_W 36                                 // 32-bit words per row
#define STAGE_BYTES_C ((BM + BN) * LDA_H * 2)    // 36864 B
#define STAGE_WORDS   ((BM + BN) * LDA_W)        // 9216 words
#define CONV_SMEM (3 * STAGE_BYTES_C)            // 110592 B

__device__ __forceinline__ void load_chunk(uint32_t sA, uint32_t sB,
                                           const __half* __restrict__ xtb,
                                           const __half* __restrict__ wbB,
                                           int chunk, int tid, int h0)
{
    int kk = chunk >> 2;                         // tap 0..8
    int c0 = (chunk & 3) * BKc;                  // channel base
    int dh = kk / 3 - 1, dw = kk % 3 - 1;
    const __half* wb = wbB + (size_t)kk * (Och * Cch);
    // A tile: 128 spatial rows x 64 halves (128 B/row = 8 x 16B)
#pragma unroll
    for (int i = 0; i < 4; i++) {
        int idx = i * 256 + tid;                 // 0..1023
        int r = idx >> 3, cq = idx & 7;
        int hh = h0 + (r >> 6) + dh;
        int ww = (r & 63) + dw;
        bool ok = ((unsigned)hh < 64u) && ((unsigned)ww < 64u);
        const __half* g = ok ? (xtb + (size_t)(hh * 64 + ww) * Cch + c0 + cq * 8) : xtb;
        cp16(sA + (uint32_t)(r * (LDA_H * 2) + cq * 16), g, ok ? 16u : 0u);
    }
    // B tile: 128 o rows x 64 halves
#pragma unroll
    for (int i = 0; i < 4; i++) {
        int idx = i * 256 + tid;
        int r = idx >> 3, cq = idx & 7;
        const __half* g = wb + (size_t)r * Cch + c0 + cq * 8;
        cp16(sB + (uint32_t)(r * (LDA_H * 2) + cq * 16), g, 16u);
    }
    CP_COMMIT();
}

__global__ __launch_bounds__(256) void conv_mma_kernel(float* __restrict__ out) {
    extern __shared__ float smf[];
    uint32_t sbase = smem_u32(smf);
    int tid = threadIdx.x;
    int wid = tid >> 5, lane = tid & 31;
    int warp_m = wid & 1;       // 2 x 64 along M
    int warp_n = wid >> 1;      // 4 x 32 along N

    int nt = blockIdx.x;
    int bn = blockIdx.y;
    int b  = blockIdx.z;
    int h0 = nt * 2;

    const __half* xtb = g_xt + (size_t)b * HW * Cch;
    const __half* wbB = g_weff + ((size_t)(b * 9) * Och + bn * BN) * Cch;

    uint32_t stA[3], stB[3];
#pragma unroll
    for (int s = 0; s < 3; s++) {
        stA[s] = sbase + (uint32_t)(s * STAGE_BYTES_C);
        stB[s] = stA[s] + (uint32_t)(BM * LDA_H * 2);
    }

    float acc[4][4][4];
#pragma unroll
    for (int i = 0; i < 4; i++)
#pragma unroll
        for (int j = 0; j < 4; j++)
#pragma unroll
            for (int k = 0; k < 4; k++) acc[i][j][k] = 0.f;

    load_chunk(stA[0], stB[0], xtb, wbB, 0, tid, h0);
    load_chunk(stA[1], stB[1], xtb, wbB, 1, tid, h0);
    CP_WAIT1();
    __syncthreads();

    int fr = lane >> 2;
    int fc = lane & 3;

#pragma unroll 1
    for (int i = 0; i < 36; i++) {
        if (i + 2 < 36) {
            int s2 = (i + 2) % 3;
            load_chunk(stA[s2], stB[s2], xtb, wbB, i + 2, tid, h0);
        } else {
            CP_COMMIT();
        }
        const uint32_t* As = (const uint32_t*)smf + (size_t)(i % 3) * STAGE_WORDS;
        const uint32_t* Bs = As + BM * LDA_W;

#pragma unroll
        for (int ks = 0; ks < 4; ks++) {           // 4 x k16 within 64-ch chunk
            int k0 = ks * 8;                       // word offset
            uint32_t af[4][4], bf[4][2];
#pragma unroll
            for (int mt = 0; mt < 4; mt++) {
                int m0 = warp_m * 64 + mt * 16;
                int w0 = (m0 + fr) * LDA_W + k0 + fc;
                af[mt][0] = As[w0];
                af[mt][1] = As[w0 + 8 * LDA_W];
                af[mt][2] = As[w0 + 4];
                af[mt][3] = As[w0 + 8 * LDA_W + 4];
            }
#pragma unroll
            for (int nt2 = 0; nt2 < 4; nt2++) {
                int n0 = warp_n * 32 + nt2 * 8;
                int w0 = (n0 + fr) * LDA_W + k0 + fc;
                bf[nt2][0] = Bs[w0];
                bf[nt2][1] = Bs[w0 + 4];
            }
#pragma unroll
            for (int mt = 0; mt < 4; mt++)
#pragma unroll
                for (int nt2 = 0; nt2 < 4; nt2++)
                    mma_f16(acc[mt][nt2], af[mt], bf[nt2]);
        }
        CP_WAIT1();
        __syncthreads();
    }

    // ---- epilogue: stage acc through smem, coalesced float4 stores ----
    float* ep = smf;
#pragma unroll
    for (int mt = 0; mt < 4; mt++) {
#pragma unroll
        for (int nt2 = 0; nt2 < 4; nt2++) {
            int rr = warp_m * 64 + mt * 16 + fr;
            int cc = warp_n * 32 + nt2 * 8 + 2 * fc;
            ep[cc * 132 + rr]           = acc[mt][nt2][0];
            ep[(cc + 1) * 132 + rr]     = acc[mt][nt2][1];
            ep[cc * 132 + rr + 8]       = acc[mt][nt2][2];
            ep[(cc + 1) * 132 + rr + 8] = acc[mt][nt2][3];
        }
    }
    __syncthreads();

    const float* bias = g_beff + b * Och + bn * BN;
    size_t obase = ((size_t)(b * Och + bn * BN)) * HW + nt * BM;
#pragma unroll
    for (int i = 0; i < 16; i++) {
        int idx = i * 256 + tid;
        int o = idx >> 5, q = idx & 31;
        float bz = bias[o];
        const float* s = ep + o * 132 + q * 4;
        float4 v = make_float4(s[0] + bz, s[1] + bz, s[2] + bz, s[3] + bz);
        *(float4*)(out + obase + (size_t)o * HW + q * 4) = v;
    }
}

// ============================================================
// launch — conv is the 4th launch (profiled slot)
// ============================================================
extern "C" void kernel_launch(void* const* d_in, const int* in_sizes, int n_in,
                              void* d_out, int out_size)
{
    const float* x        = (const float*)d_in[0];
    const float* time_emb = (const float*)d_in[1];
    const float* Wq  = (const float*)d_in[2];
    const float* bq  = (const float*)d_in[3];
    const float* Wk  = (const float*)d_in[4];
    const float* bk  = (const float*)d_in[5];
    const float* Wv  = (const float*)d_in[6];
    const float* bv  = (const float*)d_in[7];
    const float* Wm1 = (const float*)d_in[8];
    const float* bm1 = (const float*)d_in[9];
    const float* Wm2 = (const float*)d_in[10];
    const float* bm2 = (const float*)d_in[11];
    const float* Wc  = (const float*)d_in[12];
    const float* bc  = (const float*)d_in[13];
    const float* expert_w = (const float*)d_in[14];
    const float* expert_b = (const float*)d_in[15];
    float* out = (float*)d_out;

    cudaFuncSetAttribute(conv_mma_kernel, cudaFuncAttributeMaxDynamicSharedMemorySize, CONV_SMEM);

    dim3 tgrid(HW / 32, Cch / 32, Bsz);
    transpose_pool_kernel<<<tgrid, 256>>>(x);
    router_kernel<<<Bsz, 256>>>(time_emb, Wq, bq, Wk, bk, Wv, bv,
                                Wm1, bm1, Wm2, bm2, Wc, bc, expert_b);
    mix_kernel<<<(Och * Cch) / 256, 256>>>(expert_w);

    dim3 grid(HW / BM, Och / BN, Bsz);
    conv_mma_kernel<<<grid, 256, CONV_SMEM>>>(out);
}

// round 10
// speedup vs baseline: 1.7543x; 1.0065x over previous
#include <cuda_runtime.h>
#include <cuda_fp16.h>
#include <math.h>
#include <stdint.h>

// Problem constants
#define Bsz  16
#define Cch  256
#define Och  256
#define Hh   64
#define Ww   64
#define HW   4096
#define Tdim 512
#define Eexp 4

// ---------------- device scratch (static, allocation-free) ----------------
__device__ float  g_pp[Bsz * 128 * Cch];                  // [b][st][c] partial pools
__device__ float  g_rw[Bsz * Eexp];                       // [b][e]
__device__ float  g_beff[Bsz * Och];                      // [b][o]
__device__ __align__(16) __half g_weff[(size_t)Bsz * 9 * Och * Cch]; // [b][kk][o][c] fp16
__device__ __align__(16) __half g_xt[(size_t)Bsz * HW * Cch];        // [b][s][c] NHWC fp16

// ---------------- PTX helpers (sm_80-baseline only) ----------------
__device__ __forceinline__ uint32_t smem_u32(const void* p) {
    uint32_t a;
    asm("{ .reg .u64 t; cvta.to.shared.u64 t, %1; cvt.u32.u64 %0, t; }" : "=r"(a) : "l"(p));
    return a;
}
__device__ __forceinline__ void cp16(uint32_t dst, const void* src, uint32_t nbytes) {
    asm volatile("cp.async.cg.shared.global [%0], [%1], 16, %2;"
                 :: "r"(dst), "l"(src), "r"(nbytes));
}
#define CP_COMMIT() asm volatile("cp.async.commit_group;" ::: "memory")
#define CP_WAIT1()  asm volatile("cp.async.wait_group 1;" ::: "memory")

__device__ __forceinline__ void mma_f16(float* d, const uint32_t* a, const uint32_t* b) {
    asm volatile(
        "mma.sync.aligned.m16n8k16.row.col.f32.f16.f16.f32 "
        "{%0,%1,%2,%3}, {%4,%5,%6,%7}, {%8,%9}, {%0,%1,%2,%3};"
        : "+f"(d[0]), "+f"(d[1]), "+f"(d[2]), "+f"(d[3])
        : "r"(a[0]), "r"(a[1]), "r"(a[2]), "r"(a[3]), "r"(b[0]), "r"(b[1]));
}

// ============================================================
// K0: fused transpose + partial pool, coalesced fp16 stores.
// Block = (b, 32-spatial tile). Loops over 8 channel tiles,
// stages transposed halves in smem, then writes 64B/lane rows.
// SO_LD = 264 halves = 528 B per row: multiple of 16 B so the
// uint4 staging reads are aligned for every row.
// ============================================================
#define SO_LD 264
__global__ __launch_bounds__(256) void transpose_pool_kernel(const float* __restrict__ x) {
    __shared__ float tile[32][33];
    __shared__ __half s_out[32][SO_LD];
    int st = blockIdx.x;   // spatial tile 0..127
    int b  = blockIdx.y;
    int tx = threadIdx.x & 31, ty = threadIdx.x >> 5;

#pragma unroll 1
    for (int ct = 0; ct < 8; ct++) {
        const float* xp = x + ((size_t)(b * Cch + ct * 32)) * HW + st * 32;
#pragma unroll
        for (int i = 0; i < 32; i += 8)
            tile[ty + i][tx] = xp[(size_t)(ty + i) * HW + tx];   // [c_local][s_local]
        __syncthreads();
        // transpose into fp16 staging: s_out[s_local][ct*32 + c_local]
#pragma unroll
        for (int i = 0; i < 32; i += 8)
            s_out[tx][ct * 32 + ty + i] = __float2half_rn(tile[ty + i][tx]);
        // partial pool: warp ty reduces channels [ty*4, ty*4+4)
#pragma unroll
        for (int j = 0; j < 4; j++) {
            int c = ty * 4 + j;
            float s = tile[c][tx];
#pragma unroll
            for (int o = 16; o; o >>= 1) s += __shfl_down_sync(0xffffffffu, s, o);
            if (tx == 0)
                g_pp[((size_t)(b * 128 + st)) * Cch + ct * 32 + c] = s;
        }
        __syncthreads();
    }

    // coalesced write: thread t -> s = t/8, 32 halves (64 B) at seg = t%8
    int s = threadIdx.x >> 3, seg = threadIdx.x & 7;
    __half* op = g_xt + ((size_t)b * HW + st * 32 + s) * Cch + seg * 32;
    const __half* ip = &s_out[s][seg * 32];
#pragma unroll
    for (int q = 0; q < 4; q++)
        *(uint4*)(op + q * 8) = *(const uint4*)(ip + q * 8);
}

// ============================================================
// K1: router.  One block per batch sample.
// ============================================================
__global__ __launch_bounds__(256) void router_kernel(
    const float* __restrict__ te,
    const float* __restrict__ Wq, const float* __restrict__ bq,
    const float* __restrict__ Wk, const float* __restrict__ bk,
    const float* __restrict__ Wv, const float* __restrict__ bv,
    const float* __restrict__ Wm1, const float* __restrict__ bm1,
    const float* __restrict__ Wm2, const float* __restrict__ bm2,
    const float* __restrict__ Wc, const float* __restrict__ bcv,
    const float* __restrict__ expert_b)
{
    int b = blockIdx.x;
    int t = threadIdx.x;
    __shared__ float s_te[Tdim];
    __shared__ float s_pool[Cch];
    __shared__ float s_xatt[Cch];
    __shared__ float s_h1[64];
    __shared__ float s_xmix[Cch];
    __shared__ float s_rw[Eexp];

    {
        float s = 0.f;
        const float* pp = g_pp + (size_t)b * 128 * Cch + t;
#pragma unroll 4
        for (int st = 0; st < 128; st++) s += pp[(size_t)st * Cch];
        s_pool[t] = s * (1.0f / HW);
    }
    s_te[t]       = te[b * Tdim + t];
    s_te[t + 256] = te[b * Tdim + t + 256];
    __syncthreads();

    float q = bq[t];
    const float* wq = Wq + (size_t)t * Tdim;
    for (int i = 0; i < Tdim; i++) q = fmaf(wq[i], s_te[i], q);
    float kv = bk[t];
    const float* wk = Wk + (size_t)t * Cch;
    for (int i = 0; i < Cch; i++) kv = fmaf(wk[i], s_pool[i], kv);
    float v = bv[t];
    const float* wv = Wv + (size_t)t * Cch;
    for (int i = 0; i < Cch; i++) v = fmaf(wv[i], s_pool[i], v);

    float attn = 1.0f / (1.0f + expf(-(q * kv)));
    float xa = v * attn;
    s_xatt[t] = xa;
    __syncthreads();

    if (t < 64) {
        float a = bm1[t];
        const float* w = Wm1 + (size_t)t * Cch;
        for (int i = 0; i < Cch; i++) a = fmaf(w[i], s_xatt[i], a);
        s_h1[t] = 0.5f * a * (1.0f + erff(a * 0.7071067811865476f));
    }
    __syncthreads();

    float h = bm2[t];
    const float* w2 = Wm2 + (size_t)t * 64;
    for (int i = 0; i < 64; i++) h = fmaf(w2[i], s_h1[i], h);
    s_xmix[t] = xa + h;
    __syncthreads();

    if (t < Eexp) {
        float l = bcv[t];
        const float* wc = Wc + (size_t)t * Cch;
        for (int i = 0; i < Cch; i++) l = fmaf(wc[i], s_xmix[i], l);
        float r = tanhf(l);
        s_rw[t] = r;
        g_rw[b * Eexp + t] = r;
    }
    __syncthreads();

    float be = 0.f;
#pragma unroll
    for (int e = 0; e < Eexp; e++) be = fmaf(s_rw[e], expert_b[e * Och + t], be);
    g_beff[b * Och + t] = be;
}

// ============================================================
// K2: mix expert weights -> g_weff[b][kk][o][c] fp16.
// ============================================================
__global__ __launch_bounds__(256) void mix_kernel(const float* __restrict__ ew) {
    __shared__ float s_rw[Bsz * Eexp];
    if (threadIdx.x < Bsz * Eexp) s_rw[threadIdx.x] = g_rw[threadIdx.x];
    __syncthreads();

    int gid = blockIdx.x * 256 + threadIdx.x;   // 0 .. 65535
    int c = gid & 255;
    int o = gid >> 8;

    float we[Eexp][9];
#pragma unroll
    for (int e = 0; e < Eexp; e++) {
        const float* p = ew + ((size_t)((e * Och + o) * Cch + c)) * 9;
#pragma unroll
        for (int k = 0; k < 9; k++) we[e][k] = p[k];
    }
#pragma unroll 1
    for (int b = 0; b < Bsz; b++) {
        float r0 = s_rw[b * 4 + 0], r1 = s_rw[b * 4 + 1];
        float r2 = s_rw[b * 4 + 2], r3 = s_rw[b * 4 + 3];
#pragma unroll
        for (int k = 0; k < 9; k++) {
            float w = r0 * we[0][k] + r1 * we[1][k] + r2 * we[2][k] + r3 * we[3][k];
            g_weff[(((size_t)(b * 9 + k) * Och + o) << 8) + c] = __float2half_rn(w);
        }
    }
}

// ============================================================
// K3: fp16 mma.sync implicit-GEMM conv, fragment double-buffering.
// CTA tile: 128 spatial (M) x 128 O (N), K = 9*256 in 36 chunks of 64.
// 8 warps, warp tile 64x32 (m16n8k16). 3-stage cp.async pipeline.
// ============================================================
#define BM 128
#define BN 128
#define BKc 64
#define LDA_H 72                                 // halves per smem row
#define LDA_W 36                                 // 32-bit words per row
#define STAGE_BYTES_C ((BM + BN) * LDA_H * 2)    // 36864 B
#define STAGE_WORDS   ((BM + BN) * LDA_W)        // 9216 words
#define CONV_SMEM (3 * STAGE_BYTES_C)            // 110592 B

__device__ __forceinline__ void load_chunk(uint32_t sA, uint32_t sB,
                                           const __half* __restrict__ xtb,
                                           const __half* __restrict__ wbB,
                                           int chunk, int tid, int h0)
{
    int kk = chunk >> 2;                         // tap 0..8
    int c0 = (chunk & 3) * BKc;                  // channel base
    int dh = kk / 3 - 1, dw = kk % 3 - 1;
    const __half* wb = wbB + (size_t)kk * (Och * Cch);
#pragma unroll
    for (int i = 0; i < 4; i++) {
        int idx = i * 256 + tid;                 // 0..1023
        int r = idx >> 3, cq = idx & 7;
        int hh = h0 + (r >> 6) + dh;
        int ww = (r & 63) + dw;
        bool ok = ((unsigned)hh < 64u) && ((unsigned)ww < 64u);
        const __half* g = ok ? (xtb + (size_t)(hh * 64 + ww) * Cch + c0 + cq * 8) : xtb;
        cp16(sA + (uint32_t)(r * (LDA_H * 2) + cq * 16), g, ok ? 16u : 0u);
    }
#pragma unroll
    for (int i = 0; i < 4; i++) {
        int idx = i * 256 + tid;
        int r = idx >> 3, cq = idx & 7;
        const __half* g = wb + (size_t)r * Cch + c0 + cq * 8;
        cp16(sB + (uint32_t)(r * (LDA_H * 2) + cq * 16), g, 16u);
    }
    CP_COMMIT();
}

__device__ __forceinline__ void ld_frags(const uint32_t* As, const uint32_t* Bs,
                                         int ks, int warp_m, int warp_n, int fr, int fc,
                                         uint32_t af[4][4], uint32_t bf[4][2])
{
    int k0 = ks * 8;
#pragma unroll
    for (int mt = 0; mt < 4; mt++) {
        int w0 = (warp_m * 64 + mt * 16 + fr) * LDA_W + k0 + fc;
        af[mt][0] = As[w0];
        af[mt][1] = As[w0 + 8 * LDA_W];
        af[mt][2] = As[w0 + 4];
        af[mt][3] = As[w0 + 8 * LDA_W + 4];
    }
#pragma unroll
    for (int nt2 = 0; nt2 < 4; nt2++) {
        int w0 = (warp_n * 32 + nt2 * 8 + fr) * LDA_W + k0 + fc;
        bf[nt2][0] = Bs[w0];
        bf[nt2][1] = Bs[w0 + 4];
    }
}

__global__ __launch_bounds__(256, 2) void conv_mma_kernel(float* __restrict__ out) {
    extern __shared__ float smf[];
    uint32_t sbase = smem_u32(smf);
    int tid = threadIdx.x;
    int wid = tid >> 5, lane = tid & 31;
    int warp_m = wid & 1;       // 2 x 64 along M
    int warp_n = wid >> 1;      // 4 x 32 along N

    int nt = blockIdx.x;
    int bn = blockIdx.y;
    int b  = blockIdx.z;
    int h0 = nt * 2;

    const __half* xtb = g_xt + (size_t)b * HW * Cch;
    const __half* wbB = g_weff + ((size_t)(b * 9) * Och + bn * BN) * Cch;

    uint32_t stA[3], stB[3];
#pragma unroll
    for (int s = 0; s < 3; s++) {
        stA[s] = sbase + (uint32_t)(s * STAGE_BYTES_C);
        stB[s] = stA[s] + (uint32_t)(BM * LDA_H * 2);
    }

    float acc[4][4][4];
#pragma unroll
    for (int i = 0; i < 4; i++)
#pragma unroll
        for (int j = 0; j < 4; j++)
#pragma unroll
            for (int k = 0; k < 4; k++) acc[i][j][k] = 0.f;

    load_chunk(stA[0], stB[0], xtb, wbB, 0, tid, h0);
    load_chunk(stA[1], stB[1], xtb, wbB, 1, tid, h0);
    CP_WAIT1();
    __syncthreads();

    int fr = lane >> 2;
    int fc = lane & 3;

#pragma unroll 1
    for (int i = 0; i < 36; i++) {
        if (i + 2 < 36) {
            int s2 = (i + 2) % 3;
            load_chunk(stA[s2], stB[s2], xtb, wbB, i + 2, tid, h0);
        } else {
            CP_COMMIT();
        }
        const uint32_t* As = (const uint32_t*)smf + (size_t)(i % 3) * STAGE_WORDS;
        const uint32_t* Bs = As + BM * LDA_W;

        // fragment double-buffer: load ks+1 while mma'ing ks
        uint32_t af[2][4][4], bf[2][4][2];
        ld_frags(As, Bs, 0, warp_m, warp_n, fr, fc, af[0], bf[0]);
#pragma unroll
        for (int ks = 0; ks < 4; ks++) {
            if (ks < 3)
                ld_frags(As, Bs, ks + 1, warp_m, warp_n, fr, fc,
                         af[(ks + 1) & 1], bf[(ks + 1) & 1]);
#pragma unroll
            for (int mt = 0; mt < 4; mt++)
#pragma unroll
                for (int nt2 = 0; nt2 < 4; nt2++)
                    mma_f16(acc[mt][nt2], af[ks & 1][mt], bf[ks & 1][nt2]);
        }
        CP_WAIT1();
        __syncthreads();
    }

    // ---- epilogue: stage acc through smem, coalesced float4 stores ----
    float* ep = smf;
#pragma unroll
    for (int mt = 0; mt < 4; mt++) {
#pragma unroll
        for (int nt2 = 0; nt2 < 4; nt2++) {
            int rr = warp_m * 64 + mt * 16 + fr;
            int cc = warp_n * 32 + nt2 * 8 + 2 * fc;
            ep[cc * 132 + rr]           = acc[mt][nt2][0];
            ep[(cc + 1) * 132 + rr]     = acc[mt][nt2][1];
            ep[cc * 132 + rr + 8]       = acc[mt][nt2][2];
            ep[(cc + 1) * 132 + rr + 8] = acc[mt][nt2][3];
        }
    }
    __syncthreads();

    const float* bias = g_beff + b * Och + bn * BN;
    size_t obase = ((size_t)(b * Och + bn * BN)) * HW + nt * BM;
#pragma unroll
    for (int i = 0; i < 16; i++) {
        int idx = i * 256 + tid;
        int o = idx >> 5, q = idx & 31;
        float bz = bias[o];
        const float* s = ep + o * 132 + q * 4;
        float4 v = make_float4(s[0] + bz, s[1] + bz, s[2] + bz, s[3] + bz);
        *(float4*)(out + obase + (size_t)o * HW + q * 4) = v;
    }
}

// ============================================================
// launch — conv is the 4th launch (profiled slot)
// ============================================================
extern "C" void kernel_launch(void* const* d_in, const int* in_sizes, int n_in,
                              void* d_out, int out_size)
{
    const float* x        = (const float*)d_in[0];
    const float* time_emb = (const float*)d_in[1];
    const float* Wq  = (const float*)d_in[2];
    const float* bq  = (const float*)d_in[3];
    const float* Wk  = (const float*)d_in[4];
    const float* bk  = (const float*)d_in[5];
    const float* Wv  = (const float*)d_in[6];
    const float* bv  = (const float*)d_in[7];
    const float* Wm1 = (const float*)d_in[8];
    const float* bm1 = (const float*)d_in[9];
    const float* Wm2 = (const float*)d_in[10];
    const float* bm2 = (const float*)d_in[11];
    const float* Wc  = (const float*)d_in[12];
    const float* bc  = (const float*)d_in[13];
    const float* expert_w = (const float*)d_in[14];
    const float* expert_b = (const float*)d_in[15];
    float* out = (float*)d_out;

    cudaFuncSetAttribute(conv_mma_kernel, cudaFuncAttributeMaxDynamicSharedMemorySize, CONV_SMEM);

    dim3 tgrid(128, Bsz);
    transpose_pool_kernel<<<tgrid, 256>>>(x);
    router_kernel<<<Bsz, 256>>>(time_emb, Wq, bq, Wk, bk, Wv, bv,
                                Wm1, bm1, Wm2, bm2, Wc, bc, expert_b);
    mix_kernel<<<(Och * Cch) / 256, 256>>>(expert_w);

    dim3 grid(HW / BM, Och / BN, Bsz);
    conv_mma_kernel<<<grid, 256, CONV_SMEM>>>(out);
}

// round 11
// speedup vs baseline: 2.0200x; 1.1515x over previous
#include <cuda_runtime.h>
#include <cuda_fp16.h>
#include <math.h>
#include <stdint.h>

// Problem constants
#define Bsz  16
#define Cch  256
#define Och  256
#define Hh   64
#define Ww   64
#define HW   4096
#define Tdim 512
#define Eexp 4

// ---------------- device scratch (static, allocation-free) ----------------
__device__ float  g_pp[Bsz * 128 * Cch];                  // [b][st][c] partial pools
__device__ float  g_rw[Bsz * Eexp];                       // [b][e]
__device__ float  g_beff[Bsz * Och];                      // [b][o]
__device__ __align__(16) __half g_weff[(size_t)Bsz * 9 * Och * Cch]; // [b][kk][o][c] fp16
__device__ __align__(16) __half g_xt[(size_t)Bsz * HW * Cch];        // [b][s][c] NHWC fp16

// ---------------- PTX helpers (sm_80-baseline only) ----------------
__device__ __forceinline__ uint32_t smem_u32(const void* p) {
    uint32_t a;
    asm("{ .reg .u64 t; cvta.to.shared.u64 t, %1; cvt.u32.u64 %0, t; }" : "=r"(a) : "l"(p));
    return a;
}
__device__ __forceinline__ void cp16(uint32_t dst, const void* src, uint32_t nbytes) {
    asm volatile("cp.async.cg.shared.global [%0], [%1], 16, %2;"
                 :: "r"(dst), "l"(src), "r"(nbytes));
}
#define CP_COMMIT() asm volatile("cp.async.commit_group;" ::: "memory")
#define CP_WAIT1()  asm volatile("cp.async.wait_group 1;" ::: "memory")

__device__ __forceinline__ void mma_f16(float* d, const uint32_t* a, const uint32_t* b) {
    asm volatile(
        "mma.sync.aligned.m16n8k16.row.col.f32.f16.f16.f32 "
        "{%0,%1,%2,%3}, {%4,%5,%6,%7}, {%8,%9}, {%0,%1,%2,%3};"
        : "+f"(d[0]), "+f"(d[1]), "+f"(d[2]), "+f"(d[3])
        : "r"(a[0]), "r"(a[1]), "r"(a[2]), "r"(a[3]), "r"(b[0]), "r"(b[1]));
}
__device__ __forceinline__ float warp_sum(float a) {
#pragma unroll
    for (int o = 16; o; o >>= 1) a += __shfl_down_sync(0xffffffffu, a, o);
    return a;
}

// ============================================================
// K0: fused transpose + partial pool, coalesced fp16 stores.
// ============================================================
#define SO_LD 264
__global__ __launch_bounds__(256) void transpose_pool_kernel(const float* __restrict__ x) {
    __shared__ float tile[32][33];
    __shared__ __half s_out[32][SO_LD];
    int st = blockIdx.x;   // spatial tile 0..127
    int b  = blockIdx.y;
    int tx = threadIdx.x & 31, ty = threadIdx.x >> 5;

#pragma unroll 1
    for (int ct = 0; ct < 8; ct++) {
        const float* xp = x + ((size_t)(b * Cch + ct * 32)) * HW + st * 32;
#pragma unroll
        for (int i = 0; i < 32; i += 8)
            tile[ty + i][tx] = xp[(size_t)(ty + i) * HW + tx];   // [c_local][s_local]
        __syncthreads();
#pragma unroll
        for (int i = 0; i < 32; i += 8)
            s_out[tx][ct * 32 + ty + i] = __float2half_rn(tile[ty + i][tx]);
#pragma unroll
        for (int j = 0; j < 4; j++) {
            int c = ty * 4 + j;
            float s = warp_sum(tile[c][tx]);
            if (tx == 0)
                g_pp[((size_t)(b * 128 + st)) * Cch + ct * 32 + c] = s;
        }
        __syncthreads();
    }

    int s = threadIdx.x >> 3, seg = threadIdx.x & 7;
    __half* op = g_xt + ((size_t)b * HW + st * 32 + s) * Cch + seg * 32;
    const __half* ip = &s_out[s][seg * 32];
#pragma unroll
    for (int q = 0; q < 4; q++)
        *(uint4*)(op + q * 8) = *(const uint4*)(ip + q * 8);
}

// ============================================================
// K1: router — warp-cooperative (coalesced) matvecs.
// One block per batch sample, 8 warps.
// ============================================================
__global__ __launch_bounds__(256) void router_kernel(
    const float* __restrict__ te,
    const float* __restrict__ Wq, const float* __restrict__ bq,
    const float* __restrict__ Wk, const float* __restrict__ bk,
    const float* __restrict__ Wv, const float* __restrict__ bv,
    const float* __restrict__ Wm1, const float* __restrict__ bm1,
    const float* __restrict__ Wm2, const float* __restrict__ bm2,
    const float* __restrict__ Wc, const float* __restrict__ bcv,
    const float* __restrict__ expert_b)
{
    int b = blockIdx.x;
    int t = threadIdx.x;
    int wid = t >> 5, lane = t & 31;
    __shared__ float s_te[Tdim];
    __shared__ float s_pool[Cch];
    __shared__ float s_q[Cch], s_k[Cch], s_v[Cch];
    __shared__ float s_xatt[Cch];
    __shared__ float s_h1[64];
    __shared__ float s_xmix[Cch];
    __shared__ float s_rw[Eexp];

    // pooled[c]: coalesced partial-sum reduction
    {
        float s = 0.f;
        const float* pp = g_pp + (size_t)b * 128 * Cch + t;
#pragma unroll 4
        for (int st = 0; st < 128; st++) s += pp[(size_t)st * Cch];
        s_pool[t] = s * (1.0f / HW);
    }
    s_te[t]       = te[b * Tdim + t];
    s_te[t + 256] = te[b * Tdim + t + 256];
    __syncthreads();

    // q/k/v: warp computes 32 outputs; lanes stride the K dim (coalesced)
#pragma unroll 1
    for (int o = wid * 32; o < wid * 32 + 32; o++) {
        const float* wq = Wq + (size_t)o * Tdim;
        float aq = 0.f;
#pragma unroll
        for (int j = 0; j < 16; j++) aq = fmaf(wq[lane + j * 32], s_te[lane + j * 32], aq);
        const float* wk = Wk + (size_t)o * Cch;
        const float* wv = Wv + (size_t)o * Cch;
        float ak = 0.f, av = 0.f;
#pragma unroll
        for (int j = 0; j < 8; j++) {
            ak = fmaf(wk[lane + j * 32], s_pool[lane + j * 32], ak);
            av = fmaf(wv[lane + j * 32], s_pool[lane + j * 32], av);
        }
        aq = warp_sum(aq); ak = warp_sum(ak); av = warp_sum(av);
        if (lane == 0) {
            s_q[o] = aq + bq[o];
            s_k[o] = ak + bk[o];
            s_v[o] = av + bv[o];
        }
    }
    __syncthreads();

    {
        float attn = 1.0f / (1.0f + expf(-(s_q[t] * s_k[t])));
        s_xatt[t] = s_v[t] * attn;
    }
    __syncthreads();

    // Wm1 (64 outputs): each warp does 8
#pragma unroll 1
    for (int o = wid * 8; o < wid * 8 + 8; o++) {
        const float* w = Wm1 + (size_t)o * Cch;
        float a = 0.f;
#pragma unroll
        for (int j = 0; j < 8; j++) a = fmaf(w[lane + j * 32], s_xatt[lane + j * 32], a);
        a = warp_sum(a);
        if (lane == 0) {
            a += bm1[o];
            s_h1[o] = 0.5f * a * (1.0f + erff(a * 0.7071067811865476f));
        }
    }
    __syncthreads();

    // Wm2 (256 outputs, n=64): each warp does 32
#pragma unroll 1
    for (int o = wid * 32; o < wid * 32 + 32; o++) {
        const float* w = Wm2 + (size_t)o * 64;
        float a = fmaf(w[lane], s_h1[lane], 0.f);
        a = fmaf(w[lane + 32], s_h1[lane + 32], a);
        a = warp_sum(a);
        if (lane == 0) s_xmix[o] = s_xatt[o] + a + bm2[o];
    }
    __syncthreads();

    // Wc (4 outputs): warps 0-3, one output each
    if (wid < Eexp) {
        const float* w = Wc + (size_t)wid * Cch;
        float a = 0.f;
#pragma unroll
        for (int j = 0; j < 8; j++) a = fmaf(w[lane + j * 32], s_xmix[lane + j * 32], a);
        a = warp_sum(a);
        if (lane == 0) {
            float r = tanhf(a + bcv[wid]);
            s_rw[wid] = r;
            g_rw[b * Eexp + wid] = r;
        }
    }
    __syncthreads();

    float be = 0.f;
#pragma unroll
    for (int e = 0; e < Eexp; e++) be = fmaf(s_rw[e], expert_b[e * Och + t], be);
    g_beff[b * Och + t] = be;
}

// ============================================================
// K2: mix expert weights -> g_weff[b][kk][o][c] fp16.
// ============================================================
__global__ __launch_bounds__(256) void mix_kernel(const float* __restrict__ ew) {
    __shared__ float s_rw[Bsz * Eexp];
    if (threadIdx.x < Bsz * Eexp) s_rw[threadIdx.x] = g_rw[threadIdx.x];
    __syncthreads();

    int gid = blockIdx.x * 256 + threadIdx.x;   // 0 .. 65535
    int c = gid & 255;
    int o = gid >> 8;

    float we[Eexp][9];
#pragma unroll
    for (int e = 0; e < Eexp; e++) {
        const float* p = ew + ((size_t)((e * Och + o) * Cch + c)) * 9;
#pragma unroll
        for (int k = 0; k < 9; k++) we[e][k] = p[k];
    }
#pragma unroll 1
    for (int b = 0; b < Bsz; b++) {
        float r0 = s_rw[b * 4 + 0], r1 = s_rw[b * 4 + 1];
        float r2 = s_rw[b * 4 + 2], r3 = s_rw[b * 4 + 3];
#pragma unroll
        for (int k = 0; k < 9; k++) {
            float w = r0 * we[0][k] + r1 * we[1][k] + r2 * we[2][k] + r3 * we[3][k];
            g_weff[(((size_t)(b * 9 + k) * Och + o) << 8) + c] = __float2half_rn(w);
        }
    }
}

// ============================================================
// K3: fp16 mma.sync implicit-GEMM conv, fragment double-buffering.
// (unchanged from R10 — isolates the router delta)
// ============================================================
#define BM 128
#define BN 128
#define BKc 64
#define LDA_H 72
#define LDA_W 36
#define STAGE_BYTES_C ((BM + BN) * LDA_H * 2)    // 36864 B
#define STAGE_WORDS   ((BM + BN) * LDA_W)        // 9216 words
#define CONV_SMEM (3 * STAGE_BYTES_C)            // 110592 B

__device__ __forceinline__ void load_chunk(uint32_t sA, uint32_t sB,
                                           const __half* __restrict__ xtb,
                                           const __half* __restrict__ wbB,
                                           int chunk, int tid, int h0)
{
    int kk = chunk >> 2;
    int c0 = (chunk & 3) * BKc;
    int dh = kk / 3 - 1, dw = kk % 3 - 1;
    const __half* wb = wbB + (size_t)kk * (Och * Cch);
#pragma unroll
    for (int i = 0; i < 4; i++) {
        int idx = i * 256 + tid;
        int r = idx >> 3, cq = idx & 7;
        int hh = h0 + (r >> 6) + dh;
        int ww = (r & 63) + dw;
        bool ok = ((unsigned)hh < 64u) && ((unsigned)ww < 64u);
        const __half* g = ok ? (xtb + (size_t)(hh * 64 + ww) * Cch + c0 + cq * 8) : xtb;
        cp16(sA + (uint32_t)(r * (LDA_H * 2) + cq * 16), g, ok ? 16u : 0u);
    }
#pragma unroll
    for (int i = 0; i < 4; i++) {
        int idx = i * 256 + tid;
        int r = idx >> 3, cq = idx & 7;
        const __half* g = wb + (size_t)r * Cch + c0 + cq * 8;
        cp16(sB + (uint32_t)(r * (LDA_H * 2) + cq * 16), g, 16u);
    }
    CP_COMMIT();
}

__device__ __forceinline__ void ld_frags(const uint32_t* As, const uint32_t* Bs,
                                         int ks, int warp_m, int warp_n, int fr, int fc,
                                         uint32_t af[4][4], uint32_t bf[4][2])
{
    int k0 = ks * 8;
#pragma unroll
    for (int mt = 0; mt < 4; mt++) {
        int w0 = (warp_m * 64 + mt * 16 + fr) * LDA_W + k0 + fc;
        af[mt][0] = As[w0];
        af[mt][1] = As[w0 + 8 * LDA_W];
        af[mt][2] = As[w0 + 4];
        af[mt][3] = As[w0 + 8 * LDA_W + 4];
    }
#pragma unroll
    for (int nt2 = 0; nt2 < 4; nt2++) {
        int w0 = (warp_n * 32 + nt2 * 8 + fr) * LDA_W + k0 + fc;
        bf[nt2][0] = Bs[w0];
        bf[nt2][1] = Bs[w0 + 4];
    }
}

__global__ __launch_bounds__(256, 2) void conv_mma_kernel(float* __restrict__ out) {
    extern __shared__ float smf[];
    uint32_t sbase = smem_u32(smf);
    int tid = threadIdx.x;
    int wid = tid >> 5, lane = tid & 31;
    int warp_m = wid & 1;
    int warp_n = wid >> 1;

    int nt = blockIdx.x;
    int bn = blockIdx.y;
    int b  = blockIdx.z;
    int h0 = nt * 2;

    const __half* xtb = g_xt + (size_t)b * HW * Cch;
    const __half* wbB = g_weff + ((size_t)(b * 9) * Och + bn * BN) * Cch;

    uint32_t stA[3], stB[3];
#pragma unroll
    for (int s = 0; s < 3; s++) {
        stA[s] = sbase + (uint32_t)(s * STAGE_BYTES_C);
        stB[s] = stA[s] + (uint32_t)(BM * LDA_H * 2);
    }

    float acc[4][4][4];
#pragma unroll
    for (int i = 0; i < 4; i++)
#pragma unroll
        for (int j = 0; j < 4; j++)
#pragma unroll
            for (int k = 0; k < 4; k++) acc[i][j][k] = 0.f;

    load_chunk(stA[0], stB[0], xtb, wbB, 0, tid, h0);
    load_chunk(stA[1], stB[1], xtb, wbB, 1, tid, h0);
    CP_WAIT1();
    __syncthreads();

    int fr = lane >> 2;
    int fc = lane & 3;

#pragma unroll 1
    for (int i = 0; i < 36; i++) {
        if (i + 2 < 36) {
            int s2 = (i + 2) % 3;
            load_chunk(stA[s2], stB[s2], xtb, wbB, i + 2, tid, h0);
        } else {
            CP_COMMIT();
        }
        const uint32_t* As = (const uint32_t*)smf + (size_t)(i % 3) * STAGE_WORDS;
        const uint32_t* Bs = As + BM * LDA_W;

        uint32_t af[2][4][4], bf[2][4][2];
        ld_frags(As, Bs, 0, warp_m, warp_n, fr, fc, af[0], bf[0]);
#pragma unroll
        for (int ks = 0; ks < 4; ks++) {
            if (ks < 3)
                ld_frags(As, Bs, ks + 1, warp_m, warp_n, fr, fc,
                         af[(ks + 1) & 1], bf[(ks + 1) & 1]);
#pragma unroll
            for (int mt = 0; mt < 4; mt++)
#pragma unroll
                for (int nt2 = 0; nt2 < 4; nt2++)
                    mma_f16(acc[mt][nt2], af[ks & 1][mt], bf[ks & 1][nt2]);
        }
        CP_WAIT1();
        __syncthreads();
    }

    // ---- epilogue ----
    float* ep = smf;
#pragma unroll
    for (int mt = 0; mt < 4; mt++) {
#pragma unroll
        for (int nt2 = 0; nt2 < 4; nt2++) {
            int rr = warp_m * 64 + mt * 16 + fr;
            int cc = warp_n * 32 + nt2 * 8 + 2 * fc;
            ep[cc * 132 + rr]           = acc[mt][nt2][0];
            ep[(cc + 1) * 132 + rr]     = acc[mt][nt2][1];
            ep[cc * 132 + rr + 8]       = acc[mt][nt2][2];
            ep[(cc + 1) * 132 + rr + 8] = acc[mt][nt2][3];
        }
    }
    __syncthreads();

    const float* bias = g_beff + b * Och + bn * BN;
    size_t obase = ((size_t)(b * Och + bn * BN)) * HW + nt * BM;
#pragma unroll
    for (int i = 0; i < 16; i++) {
        int idx = i * 256 + tid;
        int o = idx >> 5, q = idx & 31;
        float bz = bias[o];
        const float* s = ep + o * 132 + q * 4;
        float4 v = make_float4(s[0] + bz, s[1] + bz, s[2] + bz, s[3] + bz);
        *(float4*)(out + obase + (size_t)o * HW + q * 4) = v;
    }
}

// ============================================================
// launch — conv is the 4th launch (profiled slot)
// ============================================================
extern "C" void kernel_launch(void* const* d_in, const int* in_sizes, int n_in,
                              void* d_out, int out_size)
{
    const float* x        = (const float*)d_in[0];
    const float* time_emb = (const float*)d_in[1];
    const float* Wq  = (const float*)d_in[2];
    const float* bq  = (const float*)d_in[3];
    const float* Wk  = (const float*)d_in[4];
    const float* bk  = (const float*)d_in[5];
    const float* Wv  = (const float*)d_in[6];
    const float* bv  = (const float*)d_in[7];
    const float* Wm1 = (const float*)d_in[8];
    const float* bm1 = (const float*)d_in[9];
    const float* Wm2 = (const float*)d_in[10];
    const float* bm2 = (const float*)d_in[11];
    const float* Wc  = (const float*)d_in[12];
    const float* bc  = (const float*)d_in[13];
    const float* expert_w = (const float*)d_in[14];
    const float* expert_b = (const float*)d_in[15];
    float* out = (float*)d_out;

    cudaFuncSetAttribute(conv_mma_kernel, cudaFuncAttributeMaxDynamicSharedMemorySize, CONV_SMEM);

    dim3 tgrid(128, Bsz);
    transpose_pool_kernel<<<tgrid, 256>>>(x);
    router_kernel<<<Bsz, 256>>>(time_emb, Wq, bq, Wk, bk, Wv, bv,
                                Wm1, bm1, Wm2, bm2, Wc, bc, expert_b);
    mix_kernel<<<(Och * Cch) / 256, 256>>>(expert_w);

    dim3 grid(HW / BM, Och / BN, Bsz);
    conv_mma_kernel<<<grid, 256, CONV_SMEM>>>(out);
}